// round 12
// baseline (speedup 1.0000x reference)
#include <cuda_runtime.h>

#define MAXN 131072
#define HID 128

__device__ float g_dinv[MAXN];
__device__ float g_dx[MAXN];
__device__ float g_ssum[MAXN];
__device__ float g_gsum[MAXN];
__device__ int   g_deg[MAXN];   // zero at module load; self-restored by k_dinv
__device__ float g_v[HID];      // zero at module load; self-restored by k_out

// Pass 1: in-degree histogram over destinations (proven R1 scalar form)
__global__ void k_deg(const int* __restrict__ col, int E) {
    int i = blockIdx.x * blockDim.x + threadIdx.x;
    if (i < E) atomicAdd(&g_deg[col[i]], 1);
}

// Pass 2: dinv = rsqrt(deg+1), dx = dinv*x ; zero accumulators ; reset deg
__global__ void k_dinv(const float* __restrict__ x, int n) {
    int i = blockIdx.x * blockDim.x + threadIdx.x;
    if (i < n) {
        int d = g_deg[i];
        g_deg[i] = 0;                       // restore for next graph replay
        float di = rsqrtf((float)(d + 1));
        g_dinv[i] = di;
        g_dx[i]   = di * x[i];
        g_ssum[i] = 0.0f;
        g_gsum[i] = 0.0f;
    }
}

// Pass 3: edge scatter, 1 edge/thread, SoA fp32 (proven R1 memory pattern).
//   ssum[c] += dx[r] ;  gsum[r] += dinv[c]
__global__ void k_scatter(const int* __restrict__ row,
                          const int* __restrict__ col, int E) {
    int i = blockIdx.x * blockDim.x + threadIdx.x;
    if (i < E) {
        int r = row[i];
        int c = col[i];
        atomicAdd(&g_ssum[c], g_dx[r]);
        atomicAdd(&g_gsum[r], g_dinv[c]);
    }
}

// Pass 4: v[f] = sum_r g[r] * relu(W1[f]*s[r] + b1[f])
// 256 threads/block, one 128-node tile per block, j-loop split across 2
// half-blocks (threads 0-127 do j in [0,64), threads 128-255 do [64,128)).
//   s[r] = di*(ssum[r] + dx[r]) ;  g[r] = di*(gsum[r] + di)
__global__ void __launch_bounds__(256) k_vred(const float* __restrict__ W1,
                                              const float* __restrict__ b1,
                                              int n) {
    __shared__ float sh_s[HID];
    __shared__ float sh_g[HID];
    int t    = threadIdx.x;
    int f    = t & 127;                 // feature id
    int half = t >> 7;                  // 0 or 1: which node half to reduce
    int r    = blockIdx.x * HID + f;    // tile node for the loader role

    // Split tile load: low half-block fills sh_s, high half-block fills sh_g.
    if (t < HID) {
        float sv = 0.0f;
        if (r < n) {
            float di = g_dinv[r];
            sv = di * (g_ssum[r] + g_dx[r]);
        }
        sh_s[f] = sv;
    } else {
        float gv = 0.0f;
        if (r < n) {
            float di = g_dinv[r];
            gv = di * (g_gsum[r] + di);
        }
        sh_g[f] = gv;
    }
    __syncthreads();

    float w  = W1[f];
    float bb = b1[f];
    float a0 = 0.f, a1 = 0.f, a2 = 0.f, a3 = 0.f;
    int j0 = half * 64;
    #pragma unroll
    for (int j = j0; j < j0 + 64; j += 4) {
        a0 += sh_g[j + 0] * fmaxf(fmaf(w, sh_s[j + 0], bb), 0.0f);
        a1 += sh_g[j + 1] * fmaxf(fmaf(w, sh_s[j + 1], bb), 0.0f);
        a2 += sh_g[j + 2] * fmaxf(fmaf(w, sh_s[j + 2], bb), 0.0f);
        a3 += sh_g[j + 3] * fmaxf(fmaf(w, sh_s[j + 3], bb), 0.0f);
    }
    atomicAdd(&g_v[f], (a0 + a1) + (a2 + a3));
}

// Pass 5 (single block): out[o] = b2[o] + (1/N)*sum_f v[f]*W2[f,o]; reset g_v.
__global__ void __launch_bounds__(512) k_out(const float* __restrict__ W2,
                                             const float* __restrict__ b2,
                                             float* __restrict__ out,
                                             int out_dim, float inv_n) {
    __shared__ float sv[HID];
    int t = threadIdx.x;
    if (t < HID) sv[t] = g_v[t];
    __syncthreads();
    for (int o = t; o < out_dim; o += blockDim.x) {
        float acc = 0.0f;
        #pragma unroll 16
        for (int f = 0; f < HID; f++) {
            acc += sv[f] * W2[f * out_dim + o];
        }
        out[o] = b2[o] + acc * inv_n;
    }
    __syncthreads();
    if (t < HID) g_v[t] = 0.0f;   // restore for next replay
}

extern "C" void kernel_launch(void* const* d_in, const int* in_sizes, int n_in,
                              void* d_out, int out_size) {
    const float* x    = (const float*)d_in[0];        // [N,1]
    const int*   ei   = (const int*)  d_in[1];        // [2,E]
    const float* W1   = (const float*)d_in[2];        // [1,128]
    const float* b1   = (const float*)d_in[3];        // [128]
    const float* W2   = (const float*)d_in[4];        // [128,400]
    const float* b2   = (const float*)d_in[5];        // [400]
    float*       out  = (float*)d_out;                // [400]

    int N = in_sizes[0];
    int E = in_sizes[1] / 2;
    const int* row = ei;
    const int* col = ei + E;

    int tb = 256;
    int ntile = (N + HID - 1) / HID;
    k_deg<<<(E + tb - 1) / tb, tb>>>(col, E);
    k_dinv<<<(N + tb - 1) / tb, tb>>>(x, N);
    k_scatter<<<(E + tb - 1) / tb, tb>>>(row, col, E);
    k_vred<<<ntile, 256>>>(W1, b1, N);
    k_out<<<1, 512>>>(W2, b2, out, out_size, 1.0f / (float)N);
}

// round 13
// speedup vs baseline: 1.2523x; 1.2523x over previous
#include <cuda_runtime.h>

#define MAXN 131072
#define HID 128

__device__ float g_dinv[MAXN];
__device__ float g_dx[MAXN];
__device__ float g_ssum[MAXN];
__device__ float g_gsum[MAXN];
__device__ int   g_deg[MAXN];   // zero at module load; self-restored by k_dinv
__device__ float g_v[HID];      // zero at module load; self-restored by epilogue
__device__ int   g_ctr;         // zero at module load; self-restored by epilogue

// Pass 1: in-degree histogram over destinations (proven R1 scalar form)
__global__ void k_deg(const int* __restrict__ col, int E) {
    int i = blockIdx.x * blockDim.x + threadIdx.x;
    if (i < E) atomicAdd(&g_deg[col[i]], 1);
}

// Pass 2: dinv = rsqrt(deg+1), dx = dinv*x ; zero accumulators ; reset deg
__global__ void k_dinv(const float* __restrict__ x, int n) {
    int i = blockIdx.x * blockDim.x + threadIdx.x;
    if (i < n) {
        int d = g_deg[i];
        g_deg[i] = 0;                       // restore for next graph replay
        float di = rsqrtf((float)(d + 1));
        g_dinv[i] = di;
        g_dx[i]   = di * x[i];
        g_ssum[i] = 0.0f;
        g_gsum[i] = 0.0f;
    }
}

// Pass 3: edge scatter, 1 edge/thread, SoA fp32 (proven R1 memory pattern).
//   ssum[c] += dx[r] ;  gsum[r] += dinv[c]
__global__ void k_scatter(const int* __restrict__ row,
                          const int* __restrict__ col, int E) {
    int i = blockIdx.x * blockDim.x + threadIdx.x;
    if (i < E) {
        int r = row[i];
        int c = col[i];
        atomicAdd(&g_ssum[c], g_dx[r]);
        atomicAdd(&g_gsum[r], g_dinv[c]);
    }
}

// Pass 4 (+fused pass 5): v[f] = sum_r g[r]*relu(W1[f]*s[r]+b1[f]);
// last block computes out[o] = b2[o] + (1/N)*sum_f v[f]*W2[f,o].
// One 128-node tile per block (proven R5 inner structure).
__global__ void __launch_bounds__(HID) k_vred(const float* __restrict__ W1,
                                              const float* __restrict__ b1,
                                              const float* __restrict__ W2,
                                              const float* __restrict__ b2,
                                              float* __restrict__ out,
                                              int n, int out_dim, float inv_n) {
    __shared__ float sh_s[HID];
    __shared__ float sh_g[HID];
    int f = threadIdx.x;
    int r = blockIdx.x * HID + f;

    float sv = 0.0f, gv = 0.0f;
    if (r < n) {
        float di = g_dinv[r];
        sv = di * (g_ssum[r] + g_dx[r]);
        gv = di * (g_gsum[r] + di);
    }
    sh_s[f] = sv;
    sh_g[f] = gv;
    __syncthreads();

    float w  = W1[f];
    float bb = b1[f];
    float a0 = 0.f, a1 = 0.f, a2 = 0.f, a3 = 0.f;
    #pragma unroll
    for (int j = 0; j < HID; j += 4) {
        a0 += sh_g[j + 0] * fmaxf(fmaf(w, sh_s[j + 0], bb), 0.0f);
        a1 += sh_g[j + 1] * fmaxf(fmaf(w, sh_s[j + 1], bb), 0.0f);
        a2 += sh_g[j + 2] * fmaxf(fmaf(w, sh_s[j + 2], bb), 0.0f);
        a3 += sh_g[j + 3] * fmaxf(fmaf(w, sh_s[j + 3], bb), 0.0f);
    }
    atomicAdd(&g_v[f], (a0 + a1) + (a2 + a3));

    // ---- last-block-done epilogue (replaces k_out launch) ----
    __shared__ int s_last;
    __threadfence();                       // make this block's g_v add visible
    __syncthreads();                       // all 128 adds issued before counting
    if (f == 0) {
        int prev = atomicAdd(&g_ctr, 1);
        s_last = (prev == gridDim.x - 1);
    }
    __syncthreads();
    if (!s_last) return;

    __threadfence();                       // acquire: see all blocks' g_v adds
    __shared__ float sv2[HID];
    sv2[f] = __ldcg(&g_v[f]);              // L2-coherent read (skip stale L1)
    __syncthreads();
    for (int o = f; o < out_dim; o += HID) {
        float acc = 0.0f;
        #pragma unroll 16
        for (int k = 0; k < HID; k++) {
            acc += sv2[k] * W2[k * out_dim + o];
        }
        out[o] = b2[o] + acc * inv_n;
    }
    // restore state for next graph replay
    g_v[f] = 0.0f;
    if (f == 0) g_ctr = 0;
}

extern "C" void kernel_launch(void* const* d_in, const int* in_sizes, int n_in,
                              void* d_out, int out_size) {
    const float* x    = (const float*)d_in[0];        // [N,1]
    const int*   ei   = (const int*)  d_in[1];        // [2,E]
    const float* W1   = (const float*)d_in[2];        // [1,128]
    const float* b1   = (const float*)d_in[3];        // [128]
    const float* W2   = (const float*)d_in[4];        // [128,400]
    const float* b2   = (const float*)d_in[5];        // [400]
    float*       out  = (float*)d_out;                // [400]

    int N = in_sizes[0];
    int E = in_sizes[1] / 2;
    const int* row = ei;
    const int* col = ei + E;

    int tb = 256;
    int ntile = (N + HID - 1) / HID;
    k_deg<<<(E + tb - 1) / tb, tb>>>(col, E);
    k_dinv<<<(N + tb - 1) / tb, tb>>>(x, N);
    k_scatter<<<(E + tb - 1) / tb, tb>>>(row, col, E);
    k_vred<<<ntile, HID>>>(W1, b1, W2, b2, out, N, out_size, 1.0f / (float)N);
}

// round 14
// speedup vs baseline: 1.3816x; 1.1033x over previous
#include <cuda_runtime.h>

#define MAXN 131072
#define HID 128

__device__ float g_dinv[MAXN];
__device__ float g_dx[MAXN];
__device__ float g_ssum[MAXN];
__device__ float g_gsum[MAXN];
__device__ int   g_deg[MAXN];   // zero at module load; self-restored by k_dinv
__device__ float g_v[HID];      // zero at module load; self-restored by k_out

// Pass 1: in-degree histogram over destinations (proven R1 scalar form)
__global__ void k_deg(const int* __restrict__ col, int E) {
    int i = blockIdx.x * blockDim.x + threadIdx.x;
    if (i < E) atomicAdd(&g_deg[col[i]], 1);
}

// Pass 2: dinv = rsqrt(deg+1), dx = dinv*x ; zero accumulators ; reset deg
__global__ void k_dinv(const float* __restrict__ x, int n) {
    int i = blockIdx.x * blockDim.x + threadIdx.x;
    if (i < n) {
        int d = g_deg[i];
        g_deg[i] = 0;                       // restore for next graph replay
        float di = rsqrtf((float)(d + 1));
        g_dinv[i] = di;
        g_dx[i]   = di * x[i];
        g_ssum[i] = 0.0f;
        g_gsum[i] = 0.0f;
    }
}

// Pass 3: edge scatter, 1 edge/thread, SoA fp32 (proven R1 memory pattern).
//   ssum[c] += dx[r] ;  gsum[r] += dinv[c]
__global__ void k_scatter(const int* __restrict__ row,
                          const int* __restrict__ col, int E) {
    int i = blockIdx.x * blockDim.x + threadIdx.x;
    if (i < E) {
        int r = row[i];
        int c = col[i];
        atomicAdd(&g_ssum[c], g_dx[r]);
        atomicAdd(&g_gsum[r], g_dinv[c]);
    }
}

// Pass 4: v[f] = sum_r g[r] * relu(W1[f]*s[r] + b1[f])
// One 128-node tile per block; inner loop uses float4 LDS (broadcast).
//   s[r] = di*(ssum[r] + dx[r]) ;  g[r] = di*(gsum[r] + di)
__global__ void __launch_bounds__(HID) k_vred(const float* __restrict__ W1,
                                              const float* __restrict__ b1,
                                              int n) {
    __shared__ alignas(16) float sh_s[HID];
    __shared__ alignas(16) float sh_g[HID];
    int f = threadIdx.x;
    int r = blockIdx.x * HID + f;

    float sv = 0.0f, gv = 0.0f;
    if (r < n) {
        float di = g_dinv[r];
        sv = di * (g_ssum[r] + g_dx[r]);
        gv = di * (g_gsum[r] + di);
    }
    sh_s[f] = sv;
    sh_g[f] = gv;
    __syncthreads();

    float w  = W1[f];
    float bb = b1[f];
    const float4* s4 = (const float4*)sh_s;
    const float4* g4 = (const float4*)sh_g;
    float a0 = 0.f, a1 = 0.f, a2 = 0.f, a3 = 0.f;
    #pragma unroll
    for (int j = 0; j < HID / 4; j++) {
        float4 s = s4[j];
        float4 g = g4[j];
        a0 += g.x * fmaxf(fmaf(w, s.x, bb), 0.0f);
        a1 += g.y * fmaxf(fmaf(w, s.y, bb), 0.0f);
        a2 += g.z * fmaxf(fmaf(w, s.z, bb), 0.0f);
        a3 += g.w * fmaxf(fmaf(w, s.w, bb), 0.0f);
    }
    atomicAdd(&g_v[f], (a0 + a1) + (a2 + a3));
}

// Pass 5 (single block): out[o] = b2[o] + (1/N)*sum_f v[f]*W2[f,o]; reset g_v.
__global__ void __launch_bounds__(512) k_out(const float* __restrict__ W2,
                                             const float* __restrict__ b2,
                                             float* __restrict__ out,
                                             int out_dim, float inv_n) {
    __shared__ float sv[HID];
    int t = threadIdx.x;
    if (t < HID) sv[t] = g_v[t];
    __syncthreads();
    for (int o = t; o < out_dim; o += blockDim.x) {
        float acc = 0.0f;
        #pragma unroll 16
        for (int f = 0; f < HID; f++) {
            acc += sv[f] * W2[f * out_dim + o];
        }
        out[o] = b2[o] + acc * inv_n;
    }
    __syncthreads();
    if (t < HID) g_v[t] = 0.0f;   // restore for next replay
}

extern "C" void kernel_launch(void* const* d_in, const int* in_sizes, int n_in,
                              void* d_out, int out_size) {
    const float* x    = (const float*)d_in[0];        // [N,1]
    const int*   ei   = (const int*)  d_in[1];        // [2,E]
    const float* W1   = (const float*)d_in[2];        // [1,128]
    const float* b1   = (const float*)d_in[3];        // [128]
    const float* W2   = (const float*)d_in[4];        // [128,400]
    const float* b2   = (const float*)d_in[5];        // [400]
    float*       out  = (float*)d_out;                // [400]

    int N = in_sizes[0];
    int E = in_sizes[1] / 2;
    const int* row = ei;
    const int* col = ei + E;

    int tb = 256;
    int ntile = (N + HID - 1) / HID;
    k_deg<<<(E + tb - 1) / tb, tb>>>(col, E);
    k_dinv<<<(N + tb - 1) / tb, tb>>>(x, N);
    k_scatter<<<(E + tb - 1) / tb, tb>>>(row, col, E);
    k_vred<<<ntile, HID>>>(W1, b1, N);
    k_out<<<1, 512>>>(W2, b2, out, out_size, 1.0f / (float)N);
}

// round 16
// speedup vs baseline: 1.4024x; 1.0151x over previous
#include <cuda_runtime.h>

#define MAXN 131072
#define HID 128

__device__ float g_dinv[MAXN];
__device__ float g_dx[MAXN];
__device__ float g_ssum[MAXN];
__device__ float g_gsum[MAXN];
__device__ int   g_deg[MAXN];   // zero at module load; self-restored by k_dinv
__device__ float g_v[HID];      // zero at module load; self-restored by k_out

// Pass 1: in-degree histogram over destinations. int2 index loads, 2 edges/thread.
__global__ void k_deg(const int2* __restrict__ col2, int E2,
                      const int* __restrict__ col, int E) {
    int i = blockIdx.x * blockDim.x + threadIdx.x;
    if (i < E2) {
        int2 c = col2[i];
        atomicAdd(&g_deg[c.x], 1);
        atomicAdd(&g_deg[c.y], 1);
    }
    if (i == 0 && (E & 1)) atomicAdd(&g_deg[col[E - 1]], 1);
}

// Pass 2: 4 nodes/thread, fully vectorized.
// dinv = rsqrt(deg+1), dx = dinv*x ; zero ssum/gsum ; reset deg.
// (n is padded region-safe: MAXN arrays, x read guarded per lane)
__global__ void k_dinv(const float* __restrict__ x, int n) {
    int i4 = blockIdx.x * blockDim.x + threadIdx.x;   // node/4 index
    int base = i4 * 4;
    if (base >= n) return;

    int4 d = *(const int4*)&g_deg[base];
    *(int4*)&g_deg[base] = make_int4(0, 0, 0, 0);     // restore for next replay

    float4 xv;
    if (base + 3 < n) {
        xv = *(const float4*)&x[base];
    } else {
        xv.x = x[base];
        xv.y = (base + 1 < n) ? x[base + 1] : 0.f;
        xv.z = (base + 2 < n) ? x[base + 2] : 0.f;
        xv.w = 0.f;
    }

    float4 di;
    di.x = rsqrtf((float)(d.x + 1));
    di.y = rsqrtf((float)(d.y + 1));
    di.z = rsqrtf((float)(d.z + 1));
    di.w = rsqrtf((float)(d.w + 1));

    float4 dx = make_float4(di.x * xv.x, di.y * xv.y, di.z * xv.z, di.w * xv.w);
    float4 z  = make_float4(0.f, 0.f, 0.f, 0.f);

    *(float4*)&g_dinv[base] = di;
    *(float4*)&g_dx[base]   = dx;
    *(float4*)&g_ssum[base] = z;
    *(float4*)&g_gsum[base] = z;
}

// Pass 3: edge scatter, 1 edge/thread, SoA fp32 (proven R1 memory pattern).
//   ssum[c] += dx[r] ;  gsum[r] += dinv[c]
__global__ void k_scatter(const int* __restrict__ row,
                          const int* __restrict__ col, int E) {
    int i = blockIdx.x * blockDim.x + threadIdx.x;
    if (i < E) {
        int r = row[i];
        int c = col[i];
        atomicAdd(&g_ssum[c], g_dx[r]);
        atomicAdd(&g_gsum[r], g_dinv[c]);
    }
}

// Pass 4: v[f] = sum_r g[r] * relu(W1[f]*s[r] + b1[f])
// One 128-node tile per block; float4 LDS broadcast inner loop (proven).
__global__ void __launch_bounds__(HID) k_vred(const float* __restrict__ W1,
                                              const float* __restrict__ b1,
                                              int n) {
    __shared__ alignas(16) float sh_s[HID];
    __shared__ alignas(16) float sh_g[HID];
    int f = threadIdx.x;
    int r = blockIdx.x * HID + f;

    float sv = 0.0f, gv = 0.0f;
    if (r < n) {
        float di = g_dinv[r];
        sv = di * (g_ssum[r] + g_dx[r]);
        gv = di * (g_gsum[r] + di);
    }
    sh_s[f] = sv;
    sh_g[f] = gv;
    __syncthreads();

    float w  = W1[f];
    float bb = b1[f];
    const float4* s4 = (const float4*)sh_s;
    const float4* g4 = (const float4*)sh_g;
    float a0 = 0.f, a1 = 0.f, a2 = 0.f, a3 = 0.f;
    #pragma unroll
    for (int j = 0; j < HID / 4; j++) {
        float4 s = s4[j];
        float4 g = g4[j];
        a0 += g.x * fmaxf(fmaf(w, s.x, bb), 0.0f);
        a1 += g.y * fmaxf(fmaf(w, s.y, bb), 0.0f);
        a2 += g.z * fmaxf(fmaf(w, s.z, bb), 0.0f);
        a3 += g.w * fmaxf(fmaf(w, s.w, bb), 0.0f);
    }
    atomicAdd(&g_v[f], (a0 + a1) + (a2 + a3));
}

// Pass 5 (single block): out[o] = b2[o] + (1/N)*sum_f v[f]*W2[f,o]; reset g_v.
__global__ void __launch_bounds__(512) k_out(const float* __restrict__ W2,
                                             const float* __restrict__ b2,
                                             float* __restrict__ out,
                                             int out_dim, float inv_n) {
    __shared__ float sv[HID];
    int t = threadIdx.x;
    if (t < HID) sv[t] = g_v[t];
    __syncthreads();
    for (int o = t; o < out_dim; o += blockDim.x) {
        float acc = 0.0f;
        #pragma unroll 16
        for (int f = 0; f < HID; f++) {
            acc += sv[f] * W2[f * out_dim + o];
        }
        out[o] = b2[o] + acc * inv_n;
    }
    __syncthreads();
    if (t < HID) g_v[t] = 0.0f;   // restore for next replay
}

extern "C" void kernel_launch(void* const* d_in, const int* in_sizes, int n_in,
                              void* d_out, int out_size) {
    const float* x    = (const float*)d_in[0];        // [N,1]
    const int*   ei   = (const int*)  d_in[1];        // [2,E]
    const float* W1   = (const float*)d_in[2];        // [1,128]
    const float* b1   = (const float*)d_in[3];        // [128]
    const float* W2   = (const float*)d_in[4];        // [128,400]
    const float* b2   = (const float*)d_in[5];        // [400]
    float*       out  = (float*)d_out;                // [400]

    int N = in_sizes[0];
    int E = in_sizes[1] / 2;
    const int* row = ei;
    const int* col = ei + E;
    int E2 = E / 2;
    int N4 = (N + 3) / 4;

    int tb = 256;
    int ntile = (N + HID - 1) / HID;
    k_deg<<<(E2 + tb - 1) / tb, tb>>>((const int2*)col, E2, col, E);
    k_dinv<<<(N4 + tb - 1) / tb, tb>>>(x, N);
    k_scatter<<<(E + tb - 1) / tb, tb>>>(row, col, E);
    k_vred<<<ntile, HID>>>(W1, b1, N);
    k_out<<<1, 512>>>(W2, b2, out, out_size, 1.0f / (float)N);
}